// round 13
// baseline (speedup 1.0000x reference)
#include <cuda_runtime.h>
#include <cuda_fp16.h>
#include <cstdint>

#define NT      17
#define DIN     128
#define NNODES  32768
#define ROWS    128
#define MAXWORK 274
#define SCATTER_BLOCKS (NNODES / 256)

#define A_STRIDE_H 136            // A tile stride in halves (272B) — LDSM conflict-free
#define WP_STRIDE  264            // pair-packed W row stride in u32 (264%32==8 -> conflict-free LDS.64)
#define WP_TERM_U  (32 * WP_STRIDE)     // 8448 u32 per term
#define WP_LAYER_U (2 * WP_TERM_U)      // 16896 u32 per layer
#define WP_CHUNKS  (WP_LAYER_U / 4)     // 4224 16B chunks per layer

// smem byte offsets
#define OFF_ROWIDX 0
#define OFF_B1     512
#define OFF_B2     1024
#define OFF_A      1536                    // 128*272 = 34816
#define OFF_W      (OFF_A + 34816)         // 36352
#define SMEM_BYTES (OFF_W + WP_LAYER_U * 4)   // 103936

// ---------------- allocation-free scratch ----------------
__device__ int g_count[NT];
__device__ int g_done;
__device__ int g_idx[NT * NNODES];
__device__ int4 g_work4[MAXWORK];
// Pair-packed fp16x2 W: [layer][type][ hi | lo ]
// index = (kc*4+li)*WP_STRIDE + col*2 + j ; entry = pack(W[2*k2][col], W[2*k2+1][col]),
// k2 = kc*8 + li + 4*j
__device__ uint32_t g_w[2][NT][WP_LAYER_U];

// ---------------- helpers ----------------
__device__ __forceinline__ uint32_t smem_u32(const void* p) {
    uint32_t a;
    asm("{ .reg .u64 t; cvta.to.shared.u64 t, %1; cvt.u32.u64 %0, t; }" : "=r"(a) : "l"(p));
    return a;
}

__device__ __forceinline__ void cp16(uint32_t dst, const void* src) {
    asm volatile("cp.async.cg.shared.global [%0], [%1], 16;" :: "r"(dst), "l"(src));
}

__device__ __forceinline__ void ldsm4(uint32_t* r, uint32_t addr) {
    asm volatile("ldmatrix.sync.aligned.m8n8.x4.shared.b16 {%0,%1,%2,%3}, [%4];"
                 : "=r"(r[0]), "=r"(r[1]), "=r"(r[2]), "=r"(r[3]) : "r"(addr));
}

__device__ __forceinline__ void mma_f16(float* c, const uint32_t* a, uint32_t b0, uint32_t b1) {
    asm volatile(
        "mma.sync.aligned.m16n8k16.row.col.f32.f16.f16.f32 "
        "{%0,%1,%2,%3}, {%4,%5,%6,%7}, {%8,%9}, {%0,%1,%2,%3};"
        : "+f"(c[0]), "+f"(c[1]), "+f"(c[2]), "+f"(c[3])
        : "r"(a[0]), "r"(a[1]), "r"(a[2]), "r"(a[3]), "r"(b0), "r"(b1));
}

__device__ __forceinline__ uint32_t packh2(__half a, __half b) {
    __half2 h = __halves2half2(a, b);
    return *reinterpret_cast<uint32_t*>(&h);
}

// ---------------- prep: vectorized pair-packed fp16 hi/lo split ----------------
// Thread = (t, kc, li, col4): 4 W-rows x 4 cols per layer, fully vectorized.
__global__ void prep_kernel(const float* __restrict__ W1, const float* __restrict__ W2) {
    if (blockIdx.x == 0) {
        if (threadIdx.x < NT) g_count[threadIdx.x] = 0;
        if (threadIdx.x == NT) g_done = 0;
    }
    int idx = blockIdx.x * 256 + threadIdx.x;   // grid = 17*1024/256 = 68, exact
    int t   = idx >> 10;
    int rem = idx & 1023;
    int kc  = rem >> 7;
    int li  = (rem >> 5) & 3;
    int col = (rem & 31) * 4;
    int k2a = kc * 8 + li;          // j=0
    int k2b = k2a + 4;              // j=1
    int pbase = (kc * 4 + li) * WP_STRIDE + col * 2;   // 8 consecutive u32
    size_t o = (size_t)t * 16384;
    const float* Ws[2] = { W1 + o, W2 + o };
    #pragma unroll
    for (int layer = 0; layer < 2; layer++) {
        const float* W = Ws[layer];
        float4 r0 = __ldg(reinterpret_cast<const float4*>(W + (2 * k2a)     * 128 + col));
        float4 r1 = __ldg(reinterpret_cast<const float4*>(W + (2 * k2a + 1) * 128 + col));
        float4 r2 = __ldg(reinterpret_cast<const float4*>(W + (2 * k2b)     * 128 + col));
        float4 r3 = __ldg(reinterpret_cast<const float4*>(W + (2 * k2b + 1) * 128 + col));
        uint32_t hi[8], lo[8];
        #pragma unroll
        for (int i = 0; i < 4; i++) {
            float a0 = (&r0.x)[i], a1 = (&r1.x)[i];
            float c0 = (&r2.x)[i], c1 = (&r3.x)[i];
            __half h0 = __float2half_rn(a0), h1 = __float2half_rn(a1);
            __half h2 = __float2half_rn(c0), h3 = __float2half_rn(c1);
            hi[2 * i]     = packh2(h0, h1);
            hi[2 * i + 1] = packh2(h2, h3);
            lo[2 * i]     = packh2(__float2half_rn(a0 - __half2float(h0)),
                                   __float2half_rn(a1 - __half2float(h1)));
            lo[2 * i + 1] = packh2(__float2half_rn(c0 - __half2float(h2)),
                                   __float2half_rn(c1 - __half2float(h3)));
        }
        uint32_t* dh = &g_w[layer][t][pbase];
        uint32_t* dl = dh + WP_TERM_U;
        *reinterpret_cast<uint4*>(dh)     = *reinterpret_cast<uint4*>(hi);
        *reinterpret_cast<uint4*>(dh + 4) = *reinterpret_cast<uint4*>(hi + 4);
        *reinterpret_cast<uint4*>(dl)     = *reinterpret_cast<uint4*>(lo);
        *reinterpret_cast<uint4*>(dl + 4) = *reinterpret_cast<uint4*>(lo + 4);
    }
}

// ---------------- two-level scatter + fused worklist build (last block) ----------------
__global__ void scatter_kernel(const int* __restrict__ types) {
    __shared__ int scount[NT];
    __shared__ int sbase_[NT];
    __shared__ int pref[NT + 1];
    __shared__ int isLast;
    int tid = threadIdx.x;
    if (tid < NT) scount[tid] = 0;
    __syncthreads();
    int n = blockIdx.x * blockDim.x + tid;
    int t = types[n];
    int rank = atomicAdd(&scount[t], 1);
    __syncthreads();
    if (tid < NT) sbase_[tid] = atomicAdd(&g_count[tid], scount[tid]);
    __syncthreads();
    g_idx[t * NNODES + sbase_[t] + rank] = n;

    // last-arriving block builds the compact worklist
    __threadfence();
    if (tid == 0) {
        int d = atomicAdd(&g_done, 1);
        isLast = (d == SCATTER_BLOCKS - 1);
    }
    __syncthreads();
    if (!isLast) return;
    __threadfence();
    if (tid == 0) {
        int w = 0;
        #pragma unroll
        for (int tt = 0; tt < NT; tt++) {
            pref[tt] = w;
            w += (g_count[tt] + ROWS - 1) / ROWS;
        }
        pref[NT] = w;
    }
    __syncthreads();
    int nw = pref[NT];
    for (int i = tid; i < MAXWORK; i += 256) {
        int4 e = make_int4(NT, 0, 0, 0);
        if (i < nw) {
            int tt = 0;
            while (i >= pref[tt + 1]) tt++;
            e = make_int4(tt, (i - pref[tt]) * ROWS, g_count[tt], 0);
        }
        g_work4[i] = e;
    }
}

// ---------------- W staging: linear cp.async copy of one layer ----------------
__device__ __forceinline__ void stage_w(int layer, int t, int tid, uint32_t wsm) {
    const char* src = reinterpret_cast<const char*>(g_w[layer][t]);
    #pragma unroll
    for (int i = 0; i < 17; i++) {
        int li = tid + i * 256;
        if (li < WP_CHUNKS) cp16(wsm + li * 16, src + li * 16);
    }
    asm volatile("cp.async.commit_group;" ::: "memory");
}

// ---------------- fp16 2-term GEMM, warp tile 32x64, A-prefetch ----------------
__device__ __forceinline__ void run_gemm(uint32_t sbase, const uint32_t* __restrict__ Wsm,
                                         float acc[2][8][4], int lane, int mbase, int nbase) {
    int rowA = mbase + ((lane >> 3) & 1) * 8 + (lane & 7);
    uint32_t aAddr = sbase + OFF_A + rowA * (A_STRIDE_H * 2) + (lane >> 4) * 16;
    const int li = lane & 3;
    const int cb2 = (nbase + (lane >> 2)) * 2;

    uint32_t a0[4], a1[4];
    ldsm4(a0, aAddr);
    ldsm4(a1, aAddr + 16 * (A_STRIDE_H * 2));

    #pragma unroll 2
    for (int kc = 0; kc < 8; kc++) {
        uint32_t n0[4], n1[4];
        if (kc < 7) {
            ldsm4(n0, aAddr + (kc + 1) * 32);
            ldsm4(n1, aAddr + 16 * (A_STRIDE_H * 2) + (kc + 1) * 32);
        }
        const uint32_t* Wh = Wsm + (kc * 4 + li) * WP_STRIDE + cb2;
        const uint32_t* Wl = Wh + WP_TERM_U;
        #pragma unroll
        for (int nt = 0; nt < 8; nt++) {
            uint2 bh = *reinterpret_cast<const uint2*>(Wh + nt * 16);
            uint2 bl = *reinterpret_cast<const uint2*>(Wl + nt * 16);
            mma_f16(acc[0][nt], a0, bh.x, bh.y);
            mma_f16(acc[1][nt], a1, bh.x, bh.y);
            mma_f16(acc[0][nt], a0, bl.x, bl.y);
            mma_f16(acc[1][nt], a1, bl.x, bl.y);
        }
        #pragma unroll
        for (int i = 0; i < 4; i++) { a0[i] = n0[i]; a1[i] = n1[i]; }
    }
}

extern __shared__ __align__(16) char smem[];

__global__ __launch_bounds__(256, 2) void mlp_kernel(
    const float* __restrict__ x,
    const float* __restrict__ b1,
    const float* __restrict__ b2,
    float* __restrict__ out)
{
    const int4 wk = __ldg(&g_work4[blockIdx.x]);
    const int t = wk.x;
    if (t >= NT) return;
    const int base = wk.y;
    const int cnt  = wk.z;

    const uint32_t sbase = smem_u32(smem);
    const int tid  = threadIdx.x;
    const int lane = tid & 31;
    const int warp = tid >> 5;
    const int mbase = (warp >> 1) * 32;
    const int nbase = (warp & 1) * 64;

    int*   rowidx = reinterpret_cast<int*>(smem + OFF_ROWIDX);
    float* sB1    = reinterpret_cast<float*>(smem + OFF_B1);
    float* sB2    = reinterpret_cast<float*>(smem + OFF_B2);
    const uint32_t* Wsm = reinterpret_cast<const uint32_t*>(smem + OFF_W);

    stage_w(0, t, tid, sbase + OFF_W);      // async W1 copy under gather

    if (tid < ROWS) {
        sB1[tid] = __ldg(b1 + t * DIN + tid);
        sB2[tid] = __ldg(b2 + t * DIN + tid);
    }

    // Gather x rows -> fp16 A tile (direct index, no pre-sync).
    // thread = (row = tid/2, k-half = tid&1).
    {
        int r = tid >> 1, kh = tid & 1;
        int gr = base + r;
        int g = (gr < cnt) ? __ldg(&g_idx[t * NNODES + gr]) : -1;
        if (kh == 0) rowidx[r] = g;
        uint32_t* dst = reinterpret_cast<uint32_t*>(smem + OFF_A + r * (A_STRIDE_H * 2) + kh * 128);
        if (g >= 0) {
            const float4* src = reinterpret_cast<const float4*>(x + (size_t)g * DIN + kh * 64);
            #pragma unroll
            for (int i = 0; i < 16; i++) {
                float4 v = __ldg(src + i);
                __half2 p0 = __floats2half2_rn(v.x, v.y);
                __half2 p1 = __floats2half2_rn(v.z, v.w);
                dst[2 * i]     = *reinterpret_cast<uint32_t*>(&p0);
                dst[2 * i + 1] = *reinterpret_cast<uint32_t*>(&p1);
            }
        } else {
            #pragma unroll
            for (int i = 0; i < 32; i++) dst[i] = 0u;
        }
    }

    asm volatile("cp.async.wait_group 0;" ::: "memory");
    __syncthreads();

    float acc[2][8][4];
    #pragma unroll
    for (int s = 0; s < 2; s++)
        #pragma unroll
        for (int nt = 0; nt < 8; nt++)
            #pragma unroll
            for (int i = 0; i < 4; i++) acc[s][nt][i] = 0.f;

    // ---------------- Layer 1 ----------------
    run_gemm(sbase, Wsm, acc, lane, mbase, nbase);

    __syncthreads();                    // gemm1 done reading W + A
    stage_w(1, t, tid, sbase + OFF_W);  // overlap W2 copy with epilogue

    #pragma unroll
    for (int s = 0; s < 2; s++) {
        #pragma unroll
        for (int nt = 0; nt < 8; nt++) {
            int col = nbase + nt * 8 + 2 * (lane & 3);
            float bb0 = sB1[col], bb1 = sB1[col + 1];
            int r0 = mbase + s * 16 + (lane >> 2);
            __half2 v0 = __floats2half2_rn(fmaxf(acc[s][nt][0] + bb0, 0.f),
                                           fmaxf(acc[s][nt][1] + bb1, 0.f));
            __half2 v1 = __floats2half2_rn(fmaxf(acc[s][nt][2] + bb0, 0.f),
                                           fmaxf(acc[s][nt][3] + bb1, 0.f));
            *reinterpret_cast<__half2*>(smem + OFF_A + r0 * (A_STRIDE_H * 2) + col * 2) = v0;
            *reinterpret_cast<__half2*>(smem + OFF_A + (r0 + 8) * (A_STRIDE_H * 2) + col * 2) = v1;
            acc[s][nt][0] = acc[s][nt][1] = acc[s][nt][2] = acc[s][nt][3] = 0.f;
        }
    }

    asm volatile("cp.async.wait_group 0;" ::: "memory");
    __syncthreads();                    // H visible + W2 staged

    // ---------------- Layer 2 ----------------
    run_gemm(sbase, Wsm, acc, lane, mbase, nbase);

    #pragma unroll
    for (int s = 0; s < 2; s++) {
        #pragma unroll
        for (int nt = 0; nt < 8; nt++) {
            int col = nbase + nt * 8 + 2 * (lane & 3);
            float bb0 = sB2[col], bb1 = sB2[col + 1];
            int r0 = mbase + s * 16 + (lane >> 2);
            int g0 = rowidx[r0];
            int g1 = rowidx[r0 + 8];
            if (g0 >= 0)
                *reinterpret_cast<float2*>(out + (size_t)g0 * DIN + col) =
                    make_float2(acc[s][nt][0] + bb0, acc[s][nt][1] + bb1);
            if (g1 >= 0)
                *reinterpret_cast<float2*>(out + (size_t)g1 * DIN + col) =
                    make_float2(acc[s][nt][2] + bb0, acc[s][nt][3] + bb1);
        }
    }
}

extern "C" void kernel_launch(void* const* d_in, const int* in_sizes, int n_in,
                              void* d_out, int out_size)
{
    const float* x     = (const float*)d_in[0];
    const float* W1    = (const float*)d_in[1];
    const float* b1    = (const float*)d_in[2];
    const float* W2    = (const float*)d_in[3];
    const float* b2    = (const float*)d_in[4];
    const int*   types = (const int*)  d_in[5];
    float*       out   = (float*)d_out;

    cudaFuncSetAttribute(mlp_kernel, cudaFuncAttributeMaxDynamicSharedMemorySize, SMEM_BYTES);

    prep_kernel<<<68, 256>>>(W1, W2);
    scatter_kernel<<<SCATTER_BLOCKS, 256>>>(types);
    mlp_kernel<<<MAXWORK, 256, SMEM_BYTES>>>(x, b1, b2, out);
}

// round 14
// speedup vs baseline: 1.2138x; 1.2138x over previous
#include <cuda_runtime.h>
#include <cuda_fp16.h>
#include <cstdint>

#define NT      17
#define DIN     128
#define NNODES  32768
#define ROWS    128
#define MAXWORK 274
#define SCATTER_BLOCKS 128
#define PREPW_BLOCKS   68
#define CONV_BLOCKS    1024
#define FUSED_BLOCKS   (SCATTER_BLOCKS + PREPW_BLOCKS + CONV_BLOCKS)

#define A_STRIDE_H 136            // A tile stride in halves (272B) — LDSM conflict-free
#define WP_STRIDE  264            // pair-packed W row stride in u32 (conflict-free LDS.64)
#define WP_TERM_U  (32 * WP_STRIDE)     // 8448 u32 per term
#define WP_LAYER_U (2 * WP_TERM_U)      // 16896 u32 per layer
#define W_BYTES    (WP_LAYER_U * 4)     // 67584

// smem byte offsets
#define OFF_MBAR   0
#define OFF_ROWIDX 16
#define OFF_B1     544
#define OFF_B2     1056
#define OFF_A      2048                    // 128*272 = 34816
#define OFF_W      36864                   // 16B aligned
#define SMEM_BYTES (OFF_W + W_BYTES)       // 104448

// ---------------- allocation-free scratch ----------------
__device__ int g_count[NT];
__device__ int g_done;
__device__ int g_idx[NT * NNODES];
__device__ int4 g_work4[MAXWORK];
__device__ uint32_t g_w[2][NT][WP_LAYER_U];       // pair-packed fp16x2 W (hi | lo)
__device__ uint32_t g_xh[NNODES * DIN / 2];       // x pre-converted to fp16 (packed pairs)

// ---------------- helpers ----------------
__device__ __forceinline__ uint32_t smem_u32(const void* p) {
    uint32_t a;
    asm("{ .reg .u64 t; cvta.to.shared.u64 t, %1; cvt.u32.u64 %0, t; }" : "=r"(a) : "l"(p));
    return a;
}

__device__ __forceinline__ void ldsm4(uint32_t* r, uint32_t addr) {
    asm volatile("ldmatrix.sync.aligned.m8n8.x4.shared.b16 {%0,%1,%2,%3}, [%4];"
                 : "=r"(r[0]), "=r"(r[1]), "=r"(r[2]), "=r"(r[3]) : "r"(addr));
}

__device__ __forceinline__ void mma_f16(float* c, const uint32_t* a, uint32_t b0, uint32_t b1) {
    asm volatile(
        "mma.sync.aligned.m16n8k16.row.col.f32.f16.f16.f32 "
        "{%0,%1,%2,%3}, {%4,%5,%6,%7}, {%8,%9}, {%0,%1,%2,%3};"
        : "+f"(c[0]), "+f"(c[1]), "+f"(c[2]), "+f"(c[3])
        : "r"(a[0]), "r"(a[1]), "r"(a[2]), "r"(a[3]), "r"(b0), "r"(b1));
}

__device__ __forceinline__ uint32_t packh2(__half a, __half b) {
    __half2 h = __halves2half2(a, b);
    return *reinterpret_cast<uint32_t*>(&h);
}

__device__ __forceinline__ void bulk_cp(uint32_t dst, const void* src, uint32_t bytes, uint32_t mbar) {
    asm volatile(
        "cp.async.bulk.shared::cluster.global.mbarrier::complete_tx::bytes [%0], [%1], %2, [%3];"
        :: "r"(dst), "l"(src), "r"(bytes), "r"(mbar) : "memory");
}

#define MBAR_INIT(mb, c) \
    asm volatile("mbarrier.init.shared.b64 [%0], %1;" :: "r"(mb), "r"((uint32_t)(c)) : "memory")
#define MBAR_EXPECT_TX(mb, bytes) \
    asm volatile("mbarrier.arrive.expect_tx.shared.b64 _, [%0], %1;" \
                 :: "r"(mb), "r"((uint32_t)(bytes)) : "memory")
#define MBAR_WAIT(mb, ph) do {                                                   \
    uint32_t _m = (mb), _p = (ph), _d;                                           \
    asm volatile("{\n\t.reg .pred p;\n\t"                                        \
        "mbarrier.try_wait.parity.acquire.cta.shared::cta.b64 p, [%1], %2;\n\t"  \
        "selp.b32 %0, 1, 0, p;\n\t}" : "=r"(_d) : "r"(_m), "r"(_p) : "memory");  \
    if (!_d) {                                                                   \
        asm volatile("{\n\t.reg .pred P1;\n\tWL_%=:\n\t"                         \
            "mbarrier.try_wait.parity.acquire.cta.shared::cta.b64 P1, [%0], %1, 0x989680;\n\t" \
            "@P1 bra.uni WD_%=;\n\tbra.uni WL_%=;\n\tWD_%=:\n\t}"                \
            :: "r"(_m), "r"(_p) : "memory");                                     \
    }                                                                            \
} while (0)

// ---------------- fused prep: scatter + W pack + x convert ----------------
__global__ void fused_prep(const float* __restrict__ x,
                           const float* __restrict__ W1, const float* __restrict__ W2,
                           const int* __restrict__ types)
{
    int b = blockIdx.x;
    int tid = threadIdx.x;

    if (b < SCATTER_BLOCKS) {
        // ---- two-level scatter + worklist build (last scatter block) ----
        __shared__ int scount[NT];
        __shared__ int sbase_[NT];
        __shared__ int pref[NT + 1];
        __shared__ int isLast;
        if (tid < NT) scount[tid] = 0;
        __syncthreads();
        int n = b * 256 + tid;
        int t = types[n];
        int rank = atomicAdd(&scount[t], 1);
        __syncthreads();
        if (tid < NT) sbase_[tid] = atomicAdd(&g_count[tid], scount[tid]);
        __syncthreads();
        g_idx[t * NNODES + sbase_[t] + rank] = n;

        __threadfence();
        if (tid == 0) {
            int d = atomicAdd(&g_done, 1);
            isLast = (d == SCATTER_BLOCKS - 1);
        }
        __syncthreads();
        if (!isLast) return;
        __threadfence();
        if (tid == 0) {
            int w = 0;
            #pragma unroll
            for (int tt = 0; tt < NT; tt++) {
                pref[tt] = w;
                w += (g_count[tt] + ROWS - 1) / ROWS;
            }
            pref[NT] = w;
        }
        __syncthreads();
        int nw = pref[NT];
        for (int i = tid; i < MAXWORK; i += 256) {
            int4 e = make_int4(NT, 0, 0, 0);
            if (i < nw) {
                int tt = 0;
                while (i >= pref[tt + 1]) tt++;
                e = make_int4(tt, (i - pref[tt]) * ROWS, g_count[tt], 0);
            }
            g_work4[i] = e;
        }
    } else if (b < SCATTER_BLOCKS + PREPW_BLOCKS) {
        // ---- W pack: fp16 hi/lo pair-packed ----
        int idx = (b - SCATTER_BLOCKS) * 256 + tid;
        int t   = idx >> 10;
        int rem = idx & 1023;
        int kc  = rem >> 7;
        int li  = (rem >> 5) & 3;
        int col = (rem & 31) * 4;
        int k2a = kc * 8 + li;
        int k2b = k2a + 4;
        int pbase = (kc * 4 + li) * WP_STRIDE + col * 2;
        size_t o = (size_t)t * 16384;
        const float* Ws[2] = { W1 + o, W2 + o };
        #pragma unroll
        for (int layer = 0; layer < 2; layer++) {
            const float* W = Ws[layer];
            float4 r0 = __ldg(reinterpret_cast<const float4*>(W + (2 * k2a)     * 128 + col));
            float4 r1 = __ldg(reinterpret_cast<const float4*>(W + (2 * k2a + 1) * 128 + col));
            float4 r2 = __ldg(reinterpret_cast<const float4*>(W + (2 * k2b)     * 128 + col));
            float4 r3 = __ldg(reinterpret_cast<const float4*>(W + (2 * k2b + 1) * 128 + col));
            uint32_t hi[8], lo[8];
            #pragma unroll
            for (int i = 0; i < 4; i++) {
                float a0 = (&r0.x)[i], a1 = (&r1.x)[i];
                float c0 = (&r2.x)[i], c1 = (&r3.x)[i];
                __half h0 = __float2half_rn(a0), h1 = __float2half_rn(a1);
                __half h2 = __float2half_rn(c0), h3 = __float2half_rn(c1);
                hi[2 * i]     = packh2(h0, h1);
                hi[2 * i + 1] = packh2(h2, h3);
                lo[2 * i]     = packh2(__float2half_rn(a0 - __half2float(h0)),
                                       __float2half_rn(a1 - __half2float(h1)));
                lo[2 * i + 1] = packh2(__float2half_rn(c0 - __half2float(h2)),
                                       __float2half_rn(c1 - __half2float(h3)));
            }
            uint32_t* dh = &g_w[layer][t][pbase];
            uint32_t* dl = dh + WP_TERM_U;
            *reinterpret_cast<uint4*>(dh)     = *reinterpret_cast<uint4*>(hi);
            *reinterpret_cast<uint4*>(dh + 4) = *reinterpret_cast<uint4*>(hi + 4);
            *reinterpret_cast<uint4*>(dl)     = *reinterpret_cast<uint4*>(lo);
            *reinterpret_cast<uint4*>(dl + 4) = *reinterpret_cast<uint4*>(lo + 4);
        }
    } else {
        // ---- x convert: fp32 -> packed fp16 pairs ----
        int cb = b - SCATTER_BLOCKS - PREPW_BLOCKS;
        const float4* xs = reinterpret_cast<const float4*>(x);
        uint2* xd = reinterpret_cast<uint2*>(g_xh);
        #pragma unroll
        for (int j = 0; j < 4; j++) {
            int fi = cb * 1024 + j * 256 + tid;
            float4 v = __ldg(xs + fi);
            __half2 p0 = __floats2half2_rn(v.x, v.y);
            __half2 p1 = __floats2half2_rn(v.z, v.w);
            xd[fi] = make_uint2(*reinterpret_cast<uint32_t*>(&p0),
                                *reinterpret_cast<uint32_t*>(&p1));
        }
    }
}

// ---------------- fp16 2-term GEMM, warp tile 32x64, A-prefetch ----------------
__device__ __forceinline__ void run_gemm(uint32_t sbase, const uint32_t* __restrict__ Wsm,
                                         float acc[2][8][4], int lane, int mbase, int nbase) {
    int rowA = mbase + ((lane >> 3) & 1) * 8 + (lane & 7);
    uint32_t aAddr = sbase + OFF_A + rowA * (A_STRIDE_H * 2) + (lane >> 4) * 16;
    const int li = lane & 3;
    const int cb2 = (nbase + (lane >> 2)) * 2;

    uint32_t a0[4], a1[4];
    ldsm4(a0, aAddr);
    ldsm4(a1, aAddr + 16 * (A_STRIDE_H * 2));

    #pragma unroll 2
    for (int kc = 0; kc < 8; kc++) {
        uint32_t n0[4], n1[4];
        if (kc < 7) {
            ldsm4(n0, aAddr + (kc + 1) * 32);
            ldsm4(n1, aAddr + 16 * (A_STRIDE_H * 2) + (kc + 1) * 32);
        }
        const uint32_t* Wh = Wsm + (kc * 4 + li) * WP_STRIDE + cb2;
        const uint32_t* Wl = Wh + WP_TERM_U;
        #pragma unroll
        for (int nt = 0; nt < 8; nt++) {
            uint2 bh = *reinterpret_cast<const uint2*>(Wh + nt * 16);
            uint2 bl = *reinterpret_cast<const uint2*>(Wl + nt * 16);
            mma_f16(acc[0][nt], a0, bh.x, bh.y);
            mma_f16(acc[1][nt], a1, bh.x, bh.y);
            mma_f16(acc[0][nt], a0, bl.x, bl.y);
            mma_f16(acc[1][nt], a1, bl.x, bl.y);
        }
        #pragma unroll
        for (int i = 0; i < 4; i++) { a0[i] = n0[i]; a1[i] = n1[i]; }
    }
}

extern __shared__ __align__(16) char smem[];

__global__ __launch_bounds__(256, 2) void mlp_kernel(
    const float* __restrict__ b1,
    const float* __restrict__ b2,
    float* __restrict__ out)
{
    // reset counters for the next replay (no mlp block reads g_count/g_done)
    if (blockIdx.x == 0) {
        if (threadIdx.x < NT) g_count[threadIdx.x] = 0;
        if (threadIdx.x == NT) g_done = 0;
    }

    const int4 wk = __ldg(&g_work4[blockIdx.x]);
    const int t = wk.x;
    if (t >= NT) return;
    const int base = wk.y;
    const int cnt  = wk.z;

    const uint32_t sbase = smem_u32(smem);
    const int tid  = threadIdx.x;
    const int lane = tid & 31;
    const int warp = tid >> 5;
    const int mbase = (warp >> 1) * 32;
    const int nbase = (warp & 1) * 64;

    int*   rowidx = reinterpret_cast<int*>(smem + OFF_ROWIDX);
    float* sB1    = reinterpret_cast<float*>(smem + OFF_B1);
    float* sB2    = reinterpret_cast<float*>(smem + OFF_B2);
    const uint32_t* Wsm = reinterpret_cast<const uint32_t*>(smem + OFF_W);

    if (tid == 0) MBAR_INIT(sbase + OFF_MBAR, 1);
    __syncthreads();
    if (tid == 0) {
        MBAR_EXPECT_TX(sbase + OFF_MBAR, W_BYTES);
        bulk_cp(sbase + OFF_W, g_w[0][t], W_BYTES, sbase + OFF_MBAR);   // W1 via DMA
    }

    if (tid < ROWS) {
        sB1[tid] = __ldg(b1 + t * DIN + tid);
        sB2[tid] = __ldg(b2 + t * DIN + tid);
    }

    // Gather pre-converted fp16 x rows -> A tile. thread = (row = tid/2, k-half = tid&1).
    {
        int r = tid >> 1, kh = tid & 1;
        int gr = base + r;
        int g = (gr < cnt) ? __ldg(&g_idx[t * NNODES + gr]) : -1;
        if (kh == 0) rowidx[r] = g;
        char* dst = smem + OFF_A + r * (A_STRIDE_H * 2) + kh * 128;
        if (g >= 0) {
            const uint4* src = reinterpret_cast<const uint4*>(g_xh + g * 64 + kh * 32);
            #pragma unroll
            for (int i = 0; i < 8; i++)
                *reinterpret_cast<uint4*>(dst + i * 16) = __ldg(src + i);
        } else {
            #pragma unroll
            for (int i = 0; i < 8; i++)
                *reinterpret_cast<uint4*>(dst + i * 16) = make_uint4(0, 0, 0, 0);
        }
    }
    __syncthreads();                       // A tile + rowidx + biases ready
    MBAR_WAIT(sbase + OFF_MBAR, 0);        // W1 DMA complete

    float acc[2][8][4];
    #pragma unroll
    for (int s = 0; s < 2; s++)
        #pragma unroll
        for (int nt = 0; nt < 8; nt++)
            #pragma unroll
            for (int i = 0; i < 4; i++) acc[s][nt][i] = 0.f;

    // ---------------- Layer 1 ----------------
    run_gemm(sbase, Wsm, acc, lane, mbase, nbase);

    __syncthreads();                       // gemm1 done reading W + A
    if (tid == 0) {
        asm volatile("fence.proxy.async.shared::cta;" ::: "memory");
        MBAR_EXPECT_TX(sbase + OFF_MBAR, W_BYTES);
        bulk_cp(sbase + OFF_W, g_w[1][t], W_BYTES, sbase + OFF_MBAR);   // W2 via DMA
    }

    // epilogue 1: bias + relu -> fp16 back into A tile
    #pragma unroll
    for (int s = 0; s < 2; s++) {
        #pragma unroll
        for (int nt = 0; nt < 8; nt++) {
            int col = nbase + nt * 8 + 2 * (lane & 3);
            float bb0 = sB1[col], bb1 = sB1[col + 1];
            int r0 = mbase + s * 16 + (lane >> 2);
            __half2 v0 = __floats2half2_rn(fmaxf(acc[s][nt][0] + bb0, 0.f),
                                           fmaxf(acc[s][nt][1] + bb1, 0.f));
            __half2 v1 = __floats2half2_rn(fmaxf(acc[s][nt][2] + bb0, 0.f),
                                           fmaxf(acc[s][nt][3] + bb1, 0.f));
            *reinterpret_cast<__half2*>(smem + OFF_A + r0 * (A_STRIDE_H * 2) + col * 2) = v0;
            *reinterpret_cast<__half2*>(smem + OFF_A + (r0 + 8) * (A_STRIDE_H * 2) + col * 2) = v1;
            acc[s][nt][0] = acc[s][nt][1] = acc[s][nt][2] = acc[s][nt][3] = 0.f;
        }
    }
    __syncthreads();                       // H visible
    MBAR_WAIT(sbase + OFF_MBAR, 1);        // W2 DMA complete

    // ---------------- Layer 2 ----------------
    run_gemm(sbase, Wsm, acc, lane, mbase, nbase);

    // epilogue 2: bias -> scatter to out
    #pragma unroll
    for (int s = 0; s < 2; s++) {
        #pragma unroll
        for (int nt = 0; nt < 8; nt++) {
            int col = nbase + nt * 8 + 2 * (lane & 3);
            float bb0 = sB2[col], bb1 = sB2[col + 1];
            int r0 = mbase + s * 16 + (lane >> 2);
            int g0 = rowidx[r0];
            int g1 = rowidx[r0 + 8];
            if (g0 >= 0)
                *reinterpret_cast<float2*>(out + (size_t)g0 * DIN + col) =
                    make_float2(acc[s][nt][0] + bb0, acc[s][nt][1] + bb1);
            if (g1 >= 0)
                *reinterpret_cast<float2*>(out + (size_t)g1 * DIN + col) =
                    make_float2(acc[s][nt][2] + bb0, acc[s][nt][3] + bb1);
        }
    }
}

extern "C" void kernel_launch(void* const* d_in, const int* in_sizes, int n_in,
                              void* d_out, int out_size)
{
    const float* x     = (const float*)d_in[0];
    const float* W1    = (const float*)d_in[1];
    const float* b1    = (const float*)d_in[2];
    const float* W2    = (const float*)d_in[3];
    const float* b2    = (const float*)d_in[4];
    const int*   types = (const int*)  d_in[5];
    float*       out   = (float*)d_out;

    cudaFuncSetAttribute(mlp_kernel, cudaFuncAttributeMaxDynamicSharedMemorySize, SMEM_BYTES);

    fused_prep<<<FUSED_BLOCKS, 256>>>(x, W1, W2, types);
    mlp_kernel<<<MAXWORK, 256, SMEM_BYTES>>>(b1, b2, out);
}

// round 15
// speedup vs baseline: 1.2252x; 1.0094x over previous
#include <cuda_runtime.h>
#include <cuda_fp16.h>
#include <cstdint>

#define NT      17
#define DIN     128
#define NNODES  32768
#define ROWS    128
#define MAXWORK 274
#define SCATTER_BLOCKS 128
#define PREPW_BLOCKS   68
#define CONV_BLOCKS    1024
#define FUSED_BLOCKS   (SCATTER_BLOCKS + PREPW_BLOCKS + CONV_BLOCKS)

#define A_STRIDE_H 136            // A tile stride in halves (272B) — LDSM conflict-free
#define WP_ROW_U   520            // quad-packed W row stride in u32 (520%32==8 -> conflict-free LDS.128)
#define WP_LAYER_U (32 * WP_ROW_U)      // 16640 u32 per layer
#define W_BYTES    (WP_LAYER_U * 4)     // 66560

// smem byte offsets
#define OFF_MBAR   0
#define OFF_ROWIDX 16
#define OFF_B1     544
#define OFF_B2     1056
#define OFF_A      2048                    // 128*272 = 34816
#define OFF_W      36864                   // 16B aligned
#define SMEM_BYTES (OFF_W + W_BYTES)       // 103424

// ---------------- allocation-free scratch ----------------
__device__ int g_count[NT];
__device__ int g_done;
__device__ int g_idx[NT * NNODES];
__device__ int4 g_work4[MAXWORK];
// Quad-packed fp16x2 W: per (layer,type): row = (kc*4+li), entry uint4 at col:
//   { hi_pair(k2=kc*8+li), hi_pair(k2+4), lo_pair(k2), lo_pair(k2+4) }
//   where pair(k2) = pack(W[2k2][col], W[2k2+1][col])
__device__ uint32_t g_w[2][NT][WP_LAYER_U];
__device__ uint32_t g_xh[NNODES * DIN / 2];       // x pre-converted to fp16 (packed pairs)

// ---------------- helpers ----------------
__device__ __forceinline__ uint32_t smem_u32(const void* p) {
    uint32_t a;
    asm("{ .reg .u64 t; cvta.to.shared.u64 t, %1; cvt.u32.u64 %0, t; }" : "=r"(a) : "l"(p));
    return a;
}

__device__ __forceinline__ void ldsm4(uint32_t* r, uint32_t addr) {
    asm volatile("ldmatrix.sync.aligned.m8n8.x4.shared.b16 {%0,%1,%2,%3}, [%4];"
                 : "=r"(r[0]), "=r"(r[1]), "=r"(r[2]), "=r"(r[3]) : "r"(addr));
}

__device__ __forceinline__ void mma_f16(float* c, const uint32_t* a, uint32_t b0, uint32_t b1) {
    asm volatile(
        "mma.sync.aligned.m16n8k16.row.col.f32.f16.f16.f32 "
        "{%0,%1,%2,%3}, {%4,%5,%6,%7}, {%8,%9}, {%0,%1,%2,%3};"
        : "+f"(c[0]), "+f"(c[1]), "+f"(c[2]), "+f"(c[3])
        : "r"(a[0]), "r"(a[1]), "r"(a[2]), "r"(a[3]), "r"(b0), "r"(b1));
}

__device__ __forceinline__ uint32_t packh2(__half a, __half b) {
    __half2 h = __halves2half2(a, b);
    return *reinterpret_cast<uint32_t*>(&h);
}

__device__ __forceinline__ void bulk_cp(uint32_t dst, const void* src, uint32_t bytes, uint32_t mbar) {
    asm volatile(
        "cp.async.bulk.shared::cluster.global.mbarrier::complete_tx::bytes [%0], [%1], %2, [%3];"
        :: "r"(dst), "l"(src), "r"(bytes), "r"(mbar) : "memory");
}

#define MBAR_INIT(mb, c) \
    asm volatile("mbarrier.init.shared.b64 [%0], %1;" :: "r"(mb), "r"((uint32_t)(c)) : "memory")
#define MBAR_EXPECT_TX(mb, bytes) \
    asm volatile("mbarrier.arrive.expect_tx.shared.b64 _, [%0], %1;" \
                 :: "r"(mb), "r"((uint32_t)(bytes)) : "memory")
#define MBAR_WAIT(mb, ph) do {                                                   \
    uint32_t _m = (mb), _p = (ph), _d;                                           \
    asm volatile("{\n\t.reg .pred p;\n\t"                                        \
        "mbarrier.try_wait.parity.acquire.cta.shared::cta.b64 p, [%1], %2;\n\t"  \
        "selp.b32 %0, 1, 0, p;\n\t}" : "=r"(_d) : "r"(_m), "r"(_p) : "memory");  \
    if (!_d) {                                                                   \
        asm volatile("{\n\t.reg .pred P1;\n\tWL_%=:\n\t"                         \
            "mbarrier.try_wait.parity.acquire.cta.shared::cta.b64 P1, [%0], %1, 0x989680;\n\t" \
            "@P1 bra.uni WD_%=;\n\tbra.uni WL_%=;\n\tWD_%=:\n\t}"                \
            :: "r"(_m), "r"(_p) : "memory");                                     \
    }                                                                            \
} while (0)

// ---------------- fused prep: scatter + W pack + x convert ----------------
__global__ void fused_prep(const float* __restrict__ x,
                           const float* __restrict__ W1, const float* __restrict__ W2,
                           const int* __restrict__ types)
{
    int b = blockIdx.x;
    int tid = threadIdx.x;

    if (b < SCATTER_BLOCKS) {
        // ---- two-level scatter + worklist build (last scatter block) ----
        __shared__ int scount[NT];
        __shared__ int sbase_[NT];
        __shared__ int pref[NT + 1];
        __shared__ int isLast;
        if (tid < NT) scount[tid] = 0;
        __syncthreads();
        int n = b * 256 + tid;
        int t = types[n];
        int rank = atomicAdd(&scount[t], 1);
        __syncthreads();
        if (tid < NT) sbase_[tid] = atomicAdd(&g_count[tid], scount[tid]);
        __syncthreads();
        g_idx[t * NNODES + sbase_[t] + rank] = n;

        __threadfence();
        if (tid == 0) {
            int d = atomicAdd(&g_done, 1);
            isLast = (d == SCATTER_BLOCKS - 1);
        }
        __syncthreads();
        if (!isLast) return;
        __threadfence();
        if (tid == 0) {
            int w = 0;
            #pragma unroll
            for (int tt = 0; tt < NT; tt++) {
                pref[tt] = w;
                w += (g_count[tt] + ROWS - 1) / ROWS;
            }
            pref[NT] = w;
        }
        __syncthreads();
        int nw = pref[NT];
        for (int i = tid; i < MAXWORK; i += 256) {
            int4 e = make_int4(NT, 0, 0, 0);
            if (i < nw) {
                int tt = 0;
                while (i >= pref[tt + 1]) tt++;
                e = make_int4(tt, (i - pref[tt]) * ROWS, g_count[tt], 0);
            }
            g_work4[i] = e;
        }
    } else if (b < SCATTER_BLOCKS + PREPW_BLOCKS) {
        // ---- W pack: fp16 hi/lo quad-packed ----
        int idx = (b - SCATTER_BLOCKS) * 256 + tid;
        int t   = idx >> 10;
        int rem = idx & 1023;
        int kc  = rem >> 7;
        int li  = (rem >> 5) & 3;
        int col = (rem & 31) * 4;
        int k2a = kc * 8 + li;
        int k2b = k2a + 4;
        int pbase = (kc * 4 + li) * WP_ROW_U + col * 4;
        size_t o = (size_t)t * 16384;
        const float* Ws[2] = { W1 + o, W2 + o };
        #pragma unroll
        for (int layer = 0; layer < 2; layer++) {
            const float* W = Ws[layer];
            float4 r0 = __ldg(reinterpret_cast<const float4*>(W + (2 * k2a)     * 128 + col));
            float4 r1 = __ldg(reinterpret_cast<const float4*>(W + (2 * k2a + 1) * 128 + col));
            float4 r2 = __ldg(reinterpret_cast<const float4*>(W + (2 * k2b)     * 128 + col));
            float4 r3 = __ldg(reinterpret_cast<const float4*>(W + (2 * k2b + 1) * 128 + col));
            #pragma unroll
            for (int i = 0; i < 4; i++) {
                float a0 = (&r0.x)[i], a1 = (&r1.x)[i];
                float c0 = (&r2.x)[i], c1 = (&r3.x)[i];
                __half h0 = __float2half_rn(a0), h1 = __float2half_rn(a1);
                __half h2 = __float2half_rn(c0), h3 = __float2half_rn(c1);
                uint4 v;
                v.x = packh2(h0, h1);                                   // hi pair k2a
                v.y = packh2(h2, h3);                                   // hi pair k2b
                v.z = packh2(__float2half_rn(a0 - __half2float(h0)),
                             __float2half_rn(a1 - __half2float(h1)));   // lo pair k2a
                v.w = packh2(__float2half_rn(c0 - __half2float(h2)),
                             __float2half_rn(c1 - __half2float(h3)));   // lo pair k2b
                *reinterpret_cast<uint4*>(&g_w[layer][t][pbase + i * 4]) = v;
            }
        }
    } else {
        // ---- x convert: fp32 -> packed fp16 pairs ----
        int cb = b - SCATTER_BLOCKS - PREPW_BLOCKS;
        const float4* xs = reinterpret_cast<const float4*>(x);
        uint2* xd = reinterpret_cast<uint2*>(g_xh);
        #pragma unroll
        for (int j = 0; j < 4; j++) {
            int fi = cb * 1024 + j * 256 + tid;
            float4 v = __ldg(xs + fi);
            __half2 p0 = __floats2half2_rn(v.x, v.y);
            __half2 p1 = __floats2half2_rn(v.z, v.w);
            xd[fi] = make_uint2(*reinterpret_cast<uint32_t*>(&p0),
                                *reinterpret_cast<uint32_t*>(&p1));
        }
    }
}

// ---------------- fp16 2-term GEMM, warp tile 32x64, quad-packed B ----------------
__device__ __forceinline__ void run_gemm(uint32_t sbase, const uint32_t* __restrict__ Wsm,
                                         float acc[2][8][4], int lane, int mbase, int nbase) {
    int rowA = mbase + ((lane >> 3) & 1) * 8 + (lane & 7);
    uint32_t aAddr = sbase + OFF_A + rowA * (A_STRIDE_H * 2) + (lane >> 4) * 16;
    const int li = lane & 3;
    const int cb4 = (nbase + (lane >> 2)) * 4;

    uint32_t a0[4], a1[4];
    ldsm4(a0, aAddr);
    ldsm4(a1, aAddr + 16 * (A_STRIDE_H * 2));

    #pragma unroll 2
    for (int kc = 0; kc < 8; kc++) {
        uint32_t n0[4], n1[4];
        if (kc < 7) {
            ldsm4(n0, aAddr + (kc + 1) * 32);
            ldsm4(n1, aAddr + 16 * (A_STRIDE_H * 2) + (kc + 1) * 32);
        }
        const uint32_t* Wrow = Wsm + (kc * 4 + li) * WP_ROW_U + cb4;
        #pragma unroll
        for (int nt = 0; nt < 8; nt++) {
            uint4 bq = *reinterpret_cast<const uint4*>(Wrow + nt * 32);
            mma_f16(acc[0][nt], a0, bq.x, bq.y);
            mma_f16(acc[1][nt], a1, bq.x, bq.y);
            mma_f16(acc[0][nt], a0, bq.z, bq.w);
            mma_f16(acc[1][nt], a1, bq.z, bq.w);
        }
        #pragma unroll
        for (int i = 0; i < 4; i++) { a0[i] = n0[i]; a1[i] = n1[i]; }
    }
}

extern __shared__ __align__(16) char smem[];

__global__ __launch_bounds__(256, 2) void mlp_kernel(
    const float* __restrict__ b1,
    const float* __restrict__ b2,
    float* __restrict__ out)
{
    // reset counters for the next replay (no mlp block reads g_count/g_done)
    if (blockIdx.x == 0) {
        if (threadIdx.x < NT) g_count[threadIdx.x] = 0;
        if (threadIdx.x == NT) g_done = 0;
    }

    const int4 wk = __ldg(&g_work4[blockIdx.x]);
    const int t = wk.x;
    if (t >= NT) return;
    const int base = wk.y;
    const int cnt  = wk.z;

    const uint32_t sbase = smem_u32(smem);
    const int tid  = threadIdx.x;
    const int lane = tid & 31;
    const int warp = tid >> 5;
    const int mbase = (warp >> 1) * 32;
    const int nbase = (warp & 1) * 64;

    int*   rowidx = reinterpret_cast<int*>(smem + OFF_ROWIDX);
    float* sB1    = reinterpret_cast<float*>(smem + OFF_B1);
    float* sB2    = reinterpret_cast<float*>(smem + OFF_B2);
    const uint32_t* Wsm = reinterpret_cast<const uint32_t*>(smem + OFF_W);

    if (tid == 0) MBAR_INIT(sbase + OFF_MBAR, 1);
    __syncthreads();
    if (tid == 0) {
        MBAR_EXPECT_TX(sbase + OFF_MBAR, W_BYTES);
        bulk_cp(sbase + OFF_W, g_w[0][t], W_BYTES, sbase + OFF_MBAR);   // W1 via DMA
    }

    if (tid < ROWS) {
        sB1[tid] = __ldg(b1 + t * DIN + tid);
        sB2[tid] = __ldg(b2 + t * DIN + tid);
    }

    // Gather pre-converted fp16 x rows -> A tile. thread = (row = tid/2, k-half = tid&1).
    {
        int r = tid >> 1, kh = tid & 1;
        int gr = base + r;
        int g = (gr < cnt) ? __ldg(&g_idx[t * NNODES + gr]) : -1;
        if (kh == 0) rowidx[r] = g;
        char* dst = smem + OFF_A + r * (A_STRIDE_H * 2) + kh * 128;
        if (g >= 0) {
            const uint4* src = reinterpret_cast<const uint4*>(g_xh + g * 64 + kh * 32);
            #pragma unroll
            for (int i = 0; i < 8; i++)
                *reinterpret_cast<uint4*>(dst + i * 16) = __ldg(src + i);
        } else {
            #pragma unroll
            for (int i = 0; i < 8; i++)
                *reinterpret_cast<uint4*>(dst + i * 16) = make_uint4(0, 0, 0, 0);
        }
    }
    __syncthreads();                       // A tile + rowidx + biases ready
    MBAR_WAIT(sbase + OFF_MBAR, 0);        // W1 DMA complete

    float acc[2][8][4];
    #pragma unroll
    for (int s = 0; s < 2; s++)
        #pragma unroll
        for (int nt = 0; nt < 8; nt++)
            #pragma unroll
            for (int i = 0; i < 4; i++) acc[s][nt][i] = 0.f;

    // ---------------- Layer 1 ----------------
    run_gemm(sbase, Wsm, acc, lane, mbase, nbase);

    __syncthreads();                       // gemm1 done reading W + A
    if (tid == 0) {
        asm volatile("fence.proxy.async.shared::cta;" ::: "memory");
        MBAR_EXPECT_TX(sbase + OFF_MBAR, W_BYTES);
        bulk_cp(sbase + OFF_W, g_w[1][t], W_BYTES, sbase + OFF_MBAR);   // W2 via DMA
    }

    // epilogue 1: bias + relu -> fp16 back into A tile
    #pragma unroll
    for (int s = 0; s < 2; s++) {
        #pragma unroll
        for (int nt = 0; nt < 8; nt++) {
            int col = nbase + nt * 8 + 2 * (lane & 3);
            float bb0 = sB1[col], bb1 = sB1[col + 1];
            int r0 = mbase + s * 16 + (lane >> 2);
            __half2 v0 = __floats2half2_rn(fmaxf(acc[s][nt][0] + bb0, 0.f),
                                           fmaxf(acc[s][nt][1] + bb1, 0.f));
            __half2 v1 = __floats2half2_rn(fmaxf(acc[s][nt][2] + bb0, 0.f),
                                           fmaxf(acc[s][nt][3] + bb1, 0.f));
            *reinterpret_cast<__half2*>(smem + OFF_A + r0 * (A_STRIDE_H * 2) + col * 2) = v0;
            *reinterpret_cast<__half2*>(smem + OFF_A + (r0 + 8) * (A_STRIDE_H * 2) + col * 2) = v1;
            acc[s][nt][0] = acc[s][nt][1] = acc[s][nt][2] = acc[s][nt][3] = 0.f;
        }
    }
    __syncthreads();                       // H visible
    MBAR_WAIT(sbase + OFF_MBAR, 1);        // W2 DMA complete

    // ---------------- Layer 2 ----------------
    run_gemm(sbase, Wsm, acc, lane, mbase, nbase);

    // epilogue 2: bias -> scatter to out
    #pragma unroll
    for (int s = 0; s < 2; s++) {
        #pragma unroll
        for (int nt = 0; nt < 8; nt++) {
            int col = nbase + nt * 8 + 2 * (lane & 3);
            float bb0 = sB2[col], bb1 = sB2[col + 1];
            int r0 = mbase + s * 16 + (lane >> 2);
            int g0 = rowidx[r0];
            int g1 = rowidx[r0 + 8];
            if (g0 >= 0)
                *reinterpret_cast<float2*>(out + (size_t)g0 * DIN + col) =
                    make_float2(acc[s][nt][0] + bb0, acc[s][nt][1] + bb1);
            if (g1 >= 0)
                *reinterpret_cast<float2*>(out + (size_t)g1 * DIN + col) =
                    make_float2(acc[s][nt][2] + bb0, acc[s][nt][3] + bb1);
        }
    }
}

extern "C" void kernel_launch(void* const* d_in, const int* in_sizes, int n_in,
                              void* d_out, int out_size)
{
    const float* x     = (const float*)d_in[0];
    const float* W1    = (const float*)d_in[1];
    const float* b1    = (const float*)d_in[2];
    const float* W2    = (const float*)d_in[3];
    const float* b2    = (const float*)d_in[4];
    const int*   types = (const int*)  d_in[5];
    float*       out   = (float*)d_out;

    cudaFuncSetAttribute(mlp_kernel, cudaFuncAttributeMaxDynamicSharedMemorySize, SMEM_BYTES);

    fused_prep<<<FUSED_BLOCKS, 256>>>(x, W1, W2, types);
    mlp_kernel<<<MAXWORK, 256, SMEM_BYTES>>>(b1, b2, out);
}